// round 14
// baseline (speedup 1.0000x reference)
#include <cuda_runtime.h>
#include <cuda_fp16.h>
#include <cstdint>
#include <math.h>

// -------------------- problem constants --------------------
#define BATCH   8192
#define INSZ    1024
#define HIDSZ   1024
#define KTOT    2048
#define BH      (BATCH * HIDSZ)

// -------------------- GEMM tiling --------------------
#define BM 64
#define BN 64
#define BK 64
#define KITERS (KTOT / BK)          // 32
#define RS 144                      // smem row stride bytes (128B data + 16B pad)
#define TILEA (64 * RS)             // 9216 (A, BM rows)
#define TILEB (64 * RS)             // 9216 (one gate's B, BN rows)
#define STAGE_BYTES (TILEA + 3 * TILEB)   // 36864
#define SMEM_TOTAL (2 * STAGE_BYTES)      // 73728 (3 CTAs/SM: 216KB)

// -------------------- device scratch --------------------
__device__ __align__(16) __half gAh[(size_t)BATCH * KTOT];       // A (fp16)
__device__ __align__(16) __half gW [(size_t)3 * HIDSZ * KTOT];   // W^T: [g][n][k]
__device__ __align__(16) float  g_z2[BATCH * 8];

// -------------------- streams/events for graph fork-join --------------------
namespace {
struct GraphStreams {
    cudaStream_t sW = nullptr;
    cudaEvent_t evRoot = nullptr, evW = nullptr;
    GraphStreams() {
        cudaStreamCreateWithFlags(&sW, cudaStreamNonBlocking);
        cudaEventCreateWithFlags(&evRoot, cudaEventDisableTiming);
        cudaEventCreateWithFlags(&evW, cudaEventDisableTiming);
    }
};
GraphStreams g_gs;
}

// -------------------- helpers --------------------
__device__ __forceinline__ uint32_t smem_u32(const void* p) {
    uint32_t a;
    asm("{ .reg .u64 t; cvta.to.shared.u64 t, %1; cvt.u32.u64 %0, t; }" : "=r"(a) : "l"(p));
    return a;
}
#define CPASYNC16(dst, src) \
    asm volatile("cp.async.cg.shared.global [%0], [%1], 16;" :: "r"(dst), "l"(src))
#define CP_COMMIT() asm volatile("cp.async.commit_group;")
#define CP_WAIT0()  asm volatile("cp.async.wait_group 0;")

__device__ __forceinline__ void ldmx4(uint32_t addr, uint32_t& r0, uint32_t& r1,
                                      uint32_t& r2, uint32_t& r3) {
    asm volatile("ldmatrix.sync.aligned.m8n8.x4.shared.b16 {%0,%1,%2,%3}, [%4];"
                 : "=r"(r0), "=r"(r1), "=r"(r2), "=r"(r3) : "r"(addr));
}
__device__ __forceinline__ void mma16816(float* d, const uint32_t* a, const uint32_t* b) {
    asm volatile(
        "mma.sync.aligned.m16n8k16.row.col.f32.f16.f16.f32 "
        "{%0,%1,%2,%3}, {%4,%5,%6,%7}, {%8,%9}, {%0,%1,%2,%3};"
        : "+f"(d[0]), "+f"(d[1]), "+f"(d[2]), "+f"(d[3])
        : "r"(a[0]), "r"(a[1]), "r"(a[2]), "r"(a[3]), "r"(b[0]), "r"(b[1]));
}

__device__ __forceinline__ float sigm(float x) { return 1.0f / (1.0f + __expf(-x)); }
__device__ __forceinline__ float tanh_(float x) {
    float t = __expf(2.0f * x);
    return 1.0f - 2.0f / (t + 1.0f);
}

// ---------------------------------------------------------------------------
// Fused: A = concat(x,h) -> fp16 conversion AND forget-MLP front half
// (z2 = relu(relu(xh@W1+b1)@W2+b2)).  One pass over x,h.
// grid 148 x 256 threads, 128KB smem (W1 transposed), 1 wave.
// ---------------------------------------------------------------------------
__global__ void convA_mlp(const float* __restrict__ x, const float* __restrict__ h,
                          const float* __restrict__ W1, const float* __restrict__ b1,
                          const float* __restrict__ W2, const float* __restrict__ b2)
{
    extern __shared__ float sW1T[];   // [16][2048]
    const int tid = threadIdx.x;
    for (int i = tid; i < KTOT * 16; i += blockDim.x) {
        int k = i >> 4, j = i & 15;
        sW1T[j * KTOT + k] = W1[i];
    }
    __syncthreads();

    const int warp = tid >> 5, lane = tid & 31;
    const int gw = blockIdx.x * (blockDim.x >> 5) + warp;
    const int nw = gridDim.x * (blockDim.x >> 5);

    float b1r[16];
#pragma unroll
    for (int j = 0; j < 16; j++) b1r[j] = b1[j];
    float w2r[16];
    float b2r = 0.0f;
    if (lane < 8) {
        b2r = b2[lane];
#pragma unroll
        for (int j = 0; j < 16; j++) w2r[j] = W2[j * 8 + lane];
    }

    for (int row = gw; row < BATCH; row += nw) {
        const float* xr = x + (size_t)row * INSZ;
        const float* hr = h + (size_t)row * HIDSZ;
        __half* ar = gAh + (size_t)row * KTOT;
        float acc[16];
#pragma unroll
        for (int j = 0; j < 16; j++) acc[j] = 0.0f;
#pragma unroll 4
        for (int k = lane; k < KTOT; k += 32) {
            float v = (k < INSZ) ? xr[k] : hr[k - INSZ];
            ar[k] = __float2half_rn(v);          // fused fp16 conversion
#pragma unroll
            for (int j = 0; j < 16; j++)
                acc[j] = fmaf(v, sW1T[j * KTOT + k], acc[j]);
        }
#pragma unroll
        for (int off = 16; off; off >>= 1) {
#pragma unroll
            for (int j = 0; j < 16; j++)
                acc[j] += __shfl_xor_sync(0xffffffffu, acc[j], off);
        }
        if (lane < 8) {
            float s = b2r;
#pragma unroll
            for (int j = 0; j < 16; j++)
                s = fmaf(fmaxf(acc[j] + b1r[j], 0.0f), w2r[j], s);
            g_z2[row * 8 + lane] = fmaxf(s, 0.0f);
        }
    }
}

// ---------------------------------------------------------------------------
// transpose weights: gW[g][n][k] = W[k][n]   (mat = g*2 + half, half0=Wx,1=Wh)
// ---------------------------------------------------------------------------
__global__ void convW(const float* __restrict__ Wxi, const float* __restrict__ Whi,
                      const float* __restrict__ Wxc, const float* __restrict__ Whc,
                      const float* __restrict__ Wxo, const float* __restrict__ Who) {
    __shared__ float t[32][33];
    int mat = blockIdx.z;
    const float* src;
    switch (mat) {
        case 0: src = Wxi; break; case 1: src = Whi; break;
        case 2: src = Wxc; break; case 3: src = Whc; break;
        case 4: src = Wxo; break; default: src = Who; break;
    }
    int n0 = blockIdx.x * 32, k0 = blockIdx.y * 32;
    int tx = threadIdx.x, ty = threadIdx.y;   // 32 x 8
#pragma unroll
    for (int j = 0; j < 4; j++)
        t[ty + j * 8][tx] = src[(size_t)(k0 + ty + j * 8) * HIDSZ + n0 + tx];
    __syncthreads();
    int g = mat >> 1, half = mat & 1;
#pragma unroll
    for (int j = 0; j < 4; j++) {
        int n = n0 + ty + j * 8, k = k0 + tx;
        size_t o = ((size_t)(g * HIDSZ + n)) * KTOT + half * INSZ + k;
        gW[o] = __float2half_rn(t[tx][ty + j * 8]);
    }
}

// ---------------------------------------------------------------------------
// Fused HMMA GEMM + LSTM epilogue, 2-stage pipeline, 3 CTAs/SM.
// Each CTA: 64x64 tile, ALL 3 gates, epilogue in-register, writes out.
// grid (n 16, m 128), 256 threads, warp grid 2(m) x 4(n)
// ---------------------------------------------------------------------------
__global__ __launch_bounds__(256, 3)
void gemm_fused(const float* __restrict__ c,
                const float* __restrict__ b_i, const float* __restrict__ b_c,
                const float* __restrict__ b_o,
                const float* __restrict__ W3, const float* __restrict__ b3,
                float* __restrict__ out)
{
    extern __shared__ char smem[];
    const uint32_t sbase = smem_u32(smem);

    const int tid = threadIdx.x;
    const int wid = tid >> 5, lane = tid & 31;
    const int wm = wid & 1, wn = wid >> 1;          // warp coords: 2(m) x 4(n)
    const int m0 = blockIdx.y * BM;
    const int n0 = blockIdx.x * BN;

    const __half* Ah = gAh + (size_t)m0 * KTOT;
    const __half* Bp = gW + (size_t)n0 * KTOT;       // gate g at + g*HIDSZ*KTOT

    auto copy_stage = [&](int kt, int s) {
        const uint32_t base = sbase + s * STAGE_BYTES;
        const int koff = kt * BK;
#pragma unroll
        for (int i = tid; i < 512; i += 256) {
            int row = i >> 3, ch = i & 7;
            uint32_t d = base + row * RS + ch * 16;
            const size_t go = (size_t)row * KTOT + koff + ch * 8;
            CPASYNC16(d, Ah + go);
#pragma unroll
            for (int g = 0; g < 3; g++)
                CPASYNC16(d + TILEA + g * TILEB, Bp + (size_t)g * HIDSZ * KTOT + go);
        }
    };

    float acc[3][2][2][4];
#pragma unroll
    for (int g = 0; g < 3; g++)
#pragma unroll
        for (int mt = 0; mt < 2; mt++)
#pragma unroll
            for (int nt = 0; nt < 2; nt++)
#pragma unroll
                for (int r = 0; r < 4; r++) acc[g][mt][nt][r] = 0.0f;

    // ldmatrix address components
    const uint32_t aRowOff = (uint32_t)((wm * 32 + (lane & 15)) * RS + ((lane >> 4) & 1) * 16);
    const uint32_t bRowOff = (uint32_t)((wn * 16 + (lane & 7) + ((lane >> 4) & 1) * 8) * RS
                                        + ((lane >> 3) & 1) * 16);

    copy_stage(0, 0);
    CP_COMMIT();

    for (int kt = 0; kt < KITERS; kt++) {
        const int s = kt & 1;
        CP_WAIT0();
        __syncthreads();
        if (kt + 1 < KITERS) { copy_stage(kt + 1, s ^ 1); CP_COMMIT(); }

        const uint32_t base = sbase + s * STAGE_BYTES;
        const uint32_t aB = base + aRowOff;
        const uint32_t bB = base + TILEA + bRowOff;

#pragma unroll
        for (int ks = 0; ks < 4; ks++) {
            const uint32_t kb = (uint32_t)(ks * 32);
            uint32_t a[2][4];
#pragma unroll
            for (int mt = 0; mt < 2; mt++)
                ldmx4(aB + mt * 16 * RS + kb, a[mt][0], a[mt][1], a[mt][2], a[mt][3]);
#pragma unroll
            for (int g = 0; g < 3; g++) {
                uint32_t b[4];
                ldmx4(bB + g * TILEB + kb, b[0], b[1], b[2], b[3]);   // nt 0,1
#pragma unroll
                for (int mt = 0; mt < 2; mt++)
#pragma unroll
                    for (int nt = 0; nt < 2; nt++)
                        mma16816(acc[g][mt][nt], a[mt], &b[nt * 2]);
            }
        }
        __syncthreads();
    }

    // -------------------- fused epilogue --------------------
    float* sp = (float*)smem;  // bi[64] bc[64] bo[64] b3[64] W3[8][64] z2[64][8]
    if (tid < 64) {
        sp[tid]       = b_i[n0 + tid];
        sp[64 + tid]  = b_c[n0 + tid];
        sp[128 + tid] = b_o[n0 + tid];
        sp[192 + tid] = b3[n0 + tid];
    }
    for (int i = tid; i < 512; i += 256) {
        int q = i >> 6, j = i & 63;
        sp[256 + i] = W3[q * HIDSZ + n0 + j];
    }
    if (tid < 128)
        ((float4*)(sp + 768))[tid] = ((const float4*)(g_z2 + (size_t)m0 * 8))[tid];
    __syncthreads();

    const int lr = (lane >> 2);           // 0..7
    const int lc = (lane & 3) * 2;        // 0,2,4,6
#pragma unroll
    for (int mt = 0; mt < 2; mt++)
#pragma unroll
        for (int rr = 0; rr < 2; rr++) {
            const int lrow = wm * 32 + mt * 16 + rr * 8 + lr;     // 0..63
            const int grow = m0 + lrow;
            const float* z2p = sp + 768 + lrow * 8;
#pragma unroll
            for (int nt = 0; nt < 2; nt++) {
                const int lcol = wn * 16 + nt * 8 + lc;           // 0..63
                const size_t o = (size_t)grow * HIDSZ + n0 + lcol;
                float2 cv = *(const float2*)&c[o];
                float hn[2], cn[2], fv[2];
#pragma unroll
                for (int j = 0; j < 2; j++) {
                    const int col = lcol + j;
                    float ii = sigm(acc[0][mt][nt][rr * 2 + j] + sp[col]);
                    float gg = tanh_(acc[1][mt][nt][rr * 2 + j] + sp[64 + col]);
                    float oo = sigm(acc[2][mt][nt][rr * 2 + j] + sp[128 + col]);
                    float sf = sp[192 + col];
#pragma unroll
                    for (int q = 0; q < 8; q++)
                        sf = fmaf(z2p[q], sp[256 + q * 64 + col], sf);
                    float ff = sigm(sf);
                    float cN = fmaf(ff, (j ? cv.y : cv.x), ii * gg);
                    hn[j] = oo * tanh_(cN);
                    cn[j] = cN;
                    fv[j] = ff;
                }
                *(float2*)&out[o]          = make_float2(hn[0], hn[1]);
                *(float2*)&out[BH + o]     = make_float2(cn[0], cn[1]);
                *(float2*)&out[2 * (size_t)BH + o] = make_float2(fv[0], fv[1]);
            }
        }
}

// ---------------------------------------------------------------------------
extern "C" void kernel_launch(void* const* d_in, const int* in_sizes, int n_in,
                              void* d_out, int out_size)
{
    const float* x    = (const float*)d_in[0];
    const float* h    = (const float*)d_in[1];
    const float* c    = (const float*)d_in[2];
    const float* W_hi = (const float*)d_in[3];
    const float* W_xi = (const float*)d_in[4];
    const float* b_i  = (const float*)d_in[5];
    const float* W_hc = (const float*)d_in[6];
    const float* W_xc = (const float*)d_in[7];
    const float* b_c  = (const float*)d_in[8];
    const float* W_ho = (const float*)d_in[9];
    const float* W_xo = (const float*)d_in[10];
    const float* b_o  = (const float*)d_in[11];
    const float* W1   = (const float*)d_in[12];
    const float* b1   = (const float*)d_in[13];
    const float* W2   = (const float*)d_in[14];
    const float* b2   = (const float*)d_in[15];
    const float* W3   = (const float*)d_in[16];
    const float* b3   = (const float*)d_in[17];
    float* out = (float*)d_out;

    cudaFuncSetAttribute(convA_mlp, cudaFuncAttributeMaxDynamicSharedMemorySize,
                         16 * KTOT * (int)sizeof(float));
    cudaFuncSetAttribute(gemm_fused, cudaFuncAttributeMaxDynamicSharedMemorySize,
                         SMEM_TOTAL);

    // fork: convA_mlp on main stream; convW on side stream
    cudaEventRecord(g_gs.evRoot, 0);
    cudaStreamWaitEvent(g_gs.sW, g_gs.evRoot, 0);

    convA_mlp<<<148, 256, 16 * KTOT * sizeof(float)>>>(x, h, W1, b1, W2, b2);
    convW<<<dim3(32, 32, 6), dim3(32, 8), 0, g_gs.sW>>>(W_xi, W_hi, W_xc, W_hc, W_xo, W_ho);

    // fused gemm needs convA_mlp (same stream) + convW (join)
    cudaEventRecord(g_gs.evW, g_gs.sW);
    cudaStreamWaitEvent(0, g_gs.evW, 0);

    dim3 grid(HIDSZ / BN, BATCH / BM);   // (16, 128)
    gemm_fused<<<grid, 256, SMEM_TOTAL>>>(c, b_i, b_c, b_o, W3, b3, out);
}

// round 15
// speedup vs baseline: 1.0512x; 1.0512x over previous
#include <cuda_runtime.h>
#include <cuda_fp16.h>
#include <cstdint>
#include <math.h>

// -------------------- problem constants --------------------
#define BATCH   8192
#define INSZ    1024
#define HIDSZ   1024
#define KTOT    2048
#define BH      (BATCH * HIDSZ)

// -------------------- GEMM tiling --------------------
#define BM 64
#define BN 64
#define BK 64
#define KITERS (KTOT / BK)          // 32
#define RS 144                      // smem row stride bytes (128B data + 16B pad)
#define TILEA (64 * RS)             // 9216 (A, BM rows)
#define TILEB (64 * RS)             // 9216 (one gate's B, BN rows)
#define STAGE_BYTES (TILEA + 3 * TILEB)   // 36864
#define SMEM_TOTAL (2 * STAGE_BYTES)      // 73728 (3 CTAs/SM: 216KB)

// -------------------- device scratch --------------------
__device__ __align__(16) __half gAh[(size_t)BATCH * KTOT];       // A (fp16)
__device__ __align__(16) __half gW [(size_t)3 * HIDSZ * KTOT];   // W^T: [g][n][k]
__device__ __align__(16) float  g_z2[BATCH * 8];

// -------------------- streams/events for graph fork-join --------------------
namespace {
struct GraphStreams {
    cudaStream_t sW = nullptr, sM = nullptr;
    cudaEvent_t evRoot = nullptr, evW = nullptr, evM = nullptr;
    GraphStreams() {
        cudaStreamCreateWithFlags(&sW, cudaStreamNonBlocking);
        cudaStreamCreateWithFlags(&sM, cudaStreamNonBlocking);
        cudaEventCreateWithFlags(&evRoot, cudaEventDisableTiming);
        cudaEventCreateWithFlags(&evW, cudaEventDisableTiming);
        cudaEventCreateWithFlags(&evM, cudaEventDisableTiming);
    }
};
GraphStreams g_gs;
}

// -------------------- helpers --------------------
__device__ __forceinline__ uint32_t smem_u32(const void* p) {
    uint32_t a;
    asm("{ .reg .u64 t; cvta.to.shared.u64 t, %1; cvt.u32.u64 %0, t; }" : "=r"(a) : "l"(p));
    return a;
}
#define CPASYNC16(dst, src) \
    asm volatile("cp.async.cg.shared.global [%0], [%1], 16;" :: "r"(dst), "l"(src))
#define CP_COMMIT() asm volatile("cp.async.commit_group;")
#define CP_WAIT0()  asm volatile("cp.async.wait_group 0;")

__device__ __forceinline__ void ldmx4(uint32_t addr, uint32_t& r0, uint32_t& r1,
                                      uint32_t& r2, uint32_t& r3) {
    asm volatile("ldmatrix.sync.aligned.m8n8.x4.shared.b16 {%0,%1,%2,%3}, [%4];"
                 : "=r"(r0), "=r"(r1), "=r"(r2), "=r"(r3) : "r"(addr));
}
__device__ __forceinline__ void mma16816(float* d, const uint32_t* a, const uint32_t* b) {
    asm volatile(
        "mma.sync.aligned.m16n8k16.row.col.f32.f16.f16.f32 "
        "{%0,%1,%2,%3}, {%4,%5,%6,%7}, {%8,%9}, {%0,%1,%2,%3};"
        : "+f"(d[0]), "+f"(d[1]), "+f"(d[2]), "+f"(d[3])
        : "r"(a[0]), "r"(a[1]), "r"(a[2]), "r"(a[3]), "r"(b[0]), "r"(b[1]));
}

__device__ __forceinline__ float sigm(float x) { return 1.0f / (1.0f + __expf(-x)); }
__device__ __forceinline__ float tanh_(float x) {
    float t = __expf(2.0f * x);
    return 1.0f - 2.0f / (t + 1.0f);
}

// ---------------------------------------------------------------------------
// convert A = concat(x, h) -> fp16
// ---------------------------------------------------------------------------
__global__ void convA(const float* __restrict__ x, const float* __restrict__ h) {
    int idx = blockIdx.x * blockDim.x + threadIdx.x;   // float4 index
    int row = idx >> 9;                                 // KTOT/4 = 512
    int k   = (idx & 511) * 4;
    float4 v = (k < INSZ)
        ? *(const float4*)(x + (size_t)row * INSZ + k)
        : *(const float4*)(h + (size_t)row * HIDSZ + (k - INSZ));
    size_t o = (size_t)row * KTOT + k;
    __half2* dh = (__half2*)(gAh + o);
    dh[0] = __halves2half2(__float2half_rn(v.x), __float2half_rn(v.y));
    dh[1] = __halves2half2(__float2half_rn(v.z), __float2half_rn(v.w));
}

// ---------------------------------------------------------------------------
// transpose weights: gW[g][n][k] = W[k][n]   (mat = g*2 + half, half0=Wx,1=Wh)
// ---------------------------------------------------------------------------
__global__ void convW(const float* __restrict__ Wxi, const float* __restrict__ Whi,
                      const float* __restrict__ Wxc, const float* __restrict__ Whc,
                      const float* __restrict__ Wxo, const float* __restrict__ Who) {
    __shared__ float t[32][33];
    int mat = blockIdx.z;
    const float* src;
    switch (mat) {
        case 0: src = Wxi; break; case 1: src = Whi; break;
        case 2: src = Wxc; break; case 3: src = Whc; break;
        case 4: src = Wxo; break; default: src = Who; break;
    }
    int n0 = blockIdx.x * 32, k0 = blockIdx.y * 32;
    int tx = threadIdx.x, ty = threadIdx.y;   // 32 x 8
#pragma unroll
    for (int j = 0; j < 4; j++)
        t[ty + j * 8][tx] = src[(size_t)(k0 + ty + j * 8) * HIDSZ + n0 + tx];
    __syncthreads();
    int g = mat >> 1, half = mat & 1;
#pragma unroll
    for (int j = 0; j < 4; j++) {
        int n = n0 + ty + j * 8, k = k0 + tx;
        size_t o = ((size_t)(g * HIDSZ + n)) * KTOT + half * INSZ + k;
        gW[o] = __float2half_rn(t[tx][ty + j * 8]);
    }
}

// ---------------------------------------------------------------------------
// forget-gate MLP front half: z2 = relu(relu(xh@W1+b1)@W2+b2)
// ---------------------------------------------------------------------------
__global__ void mlp_kernel(const float* __restrict__ x, const float* __restrict__ h,
                           const float* __restrict__ W1, const float* __restrict__ b1,
                           const float* __restrict__ W2, const float* __restrict__ b2)
{
    extern __shared__ float sW1T[];   // [16][2048]
    const int tid = threadIdx.x;
    for (int i = tid; i < KTOT * 16; i += blockDim.x) {
        int k = i >> 4, j = i & 15;
        sW1T[j * KTOT + k] = W1[i];
    }
    __syncthreads();

    const int warp = tid >> 5, lane = tid & 31;
    const int gw = blockIdx.x * (blockDim.x >> 5) + warp;
    const int nw = gridDim.x * (blockDim.x >> 5);

    float b1r[16];
#pragma unroll
    for (int j = 0; j < 16; j++) b1r[j] = b1[j];
    float w2r[16];
    float b2r = 0.0f;
    if (lane < 8) {
        b2r = b2[lane];
#pragma unroll
        for (int j = 0; j < 16; j++) w2r[j] = W2[j * 8 + lane];
    }

    for (int row = gw; row < BATCH; row += nw) {
        const float* xr = x + (size_t)row * INSZ;
        const float* hr = h + (size_t)row * HIDSZ;
        float acc[16];
#pragma unroll
        for (int j = 0; j < 16; j++) acc[j] = 0.0f;
#pragma unroll 4
        for (int k = lane; k < KTOT; k += 32) {
            float v = (k < INSZ) ? xr[k] : hr[k - INSZ];
#pragma unroll
            for (int j = 0; j < 16; j++)
                acc[j] = fmaf(v, sW1T[j * KTOT + k], acc[j]);
        }
#pragma unroll
        for (int off = 16; off; off >>= 1) {
#pragma unroll
            for (int j = 0; j < 16; j++)
                acc[j] += __shfl_xor_sync(0xffffffffu, acc[j], off);
        }
        if (lane < 8) {
            float s = b2r;
#pragma unroll
            for (int j = 0; j < 16; j++)
                s = fmaf(fmaxf(acc[j] + b1r[j], 0.0f), w2r[j], s);
            g_z2[row * 8 + lane] = fmaxf(s, 0.0f);
        }
    }
}

// ---------------------------------------------------------------------------
// Fused HMMA GEMM + LSTM epilogue, 2-stage pipeline, 3 CTAs/SM.
// Each CTA: 64x64 tile, ALL 3 gates, epilogue in-register, writes out.
// grid (n 16, m 128), 256 threads, warp grid 2(m) x 4(n)
// ---------------------------------------------------------------------------
__global__ __launch_bounds__(256, 3)
void gemm_fused(const float* __restrict__ c,
                const float* __restrict__ b_i, const float* __restrict__ b_c,
                const float* __restrict__ b_o,
                const float* __restrict__ W3, const float* __restrict__ b3,
                float* __restrict__ out)
{
    extern __shared__ char smem[];
    const uint32_t sbase = smem_u32(smem);

    const int tid = threadIdx.x;
    const int wid = tid >> 5, lane = tid & 31;
    const int wm = wid & 1, wn = wid >> 1;          // warp coords: 2(m) x 4(n)
    const int m0 = blockIdx.y * BM;
    const int n0 = blockIdx.x * BN;

    const __half* Ah = gAh + (size_t)m0 * KTOT;
    const __half* Bp = gW + (size_t)n0 * KTOT;       // gate g at + g*HIDSZ*KTOT

    auto copy_stage = [&](int kt, int s) {
        const uint32_t base = sbase + s * STAGE_BYTES;
        const int koff = kt * BK;
#pragma unroll
        for (int i = tid; i < 512; i += 256) {
            int row = i >> 3, ch = i & 7;
            uint32_t d = base + row * RS + ch * 16;
            const size_t go = (size_t)row * KTOT + koff + ch * 8;
            CPASYNC16(d, Ah + go);
#pragma unroll
            for (int g = 0; g < 3; g++)
                CPASYNC16(d + TILEA + g * TILEB, Bp + (size_t)g * HIDSZ * KTOT + go);
        }
    };

    float acc[3][2][2][4];
#pragma unroll
    for (int g = 0; g < 3; g++)
#pragma unroll
        for (int mt = 0; mt < 2; mt++)
#pragma unroll
            for (int nt = 0; nt < 2; nt++)
#pragma unroll
                for (int r = 0; r < 4; r++) acc[g][mt][nt][r] = 0.0f;

    // ldmatrix address components
    const uint32_t aRowOff = (uint32_t)((wm * 32 + (lane & 15)) * RS + ((lane >> 4) & 1) * 16);
    const uint32_t bRowOff = (uint32_t)((wn * 16 + (lane & 7) + ((lane >> 4) & 1) * 8) * RS
                                        + ((lane >> 3) & 1) * 16);

    copy_stage(0, 0);
    CP_COMMIT();

    for (int kt = 0; kt < KITERS; kt++) {
        const int s = kt & 1;
        CP_WAIT0();
        __syncthreads();
        if (kt + 1 < KITERS) { copy_stage(kt + 1, s ^ 1); CP_COMMIT(); }

        const uint32_t base = sbase + s * STAGE_BYTES;
        const uint32_t aB = base + aRowOff;
        const uint32_t bB = base + TILEA + bRowOff;

#pragma unroll
        for (int ks = 0; ks < 4; ks++) {
            const uint32_t kb = (uint32_t)(ks * 32);
            uint32_t a[2][4];
#pragma unroll
            for (int mt = 0; mt < 2; mt++)
                ldmx4(aB + mt * 16 * RS + kb, a[mt][0], a[mt][1], a[mt][2], a[mt][3]);
#pragma unroll
            for (int g = 0; g < 3; g++) {
                uint32_t b[4];
                ldmx4(bB + g * TILEB + kb, b[0], b[1], b[2], b[3]);   // nt 0,1
#pragma unroll
                for (int mt = 0; mt < 2; mt++)
#pragma unroll
                    for (int nt = 0; nt < 2; nt++)
                        mma16816(acc[g][mt][nt], a[mt], &b[nt * 2]);
            }
        }
        __syncthreads();
    }

    // -------------------- fused epilogue --------------------
    float* sp = (float*)smem;  // bi[64] bc[64] bo[64] b3[64] W3[8][64] z2[64][8]
    if (tid < 64) {
        sp[tid]       = b_i[n0 + tid];
        sp[64 + tid]  = b_c[n0 + tid];
        sp[128 + tid] = b_o[n0 + tid];
        sp[192 + tid] = b3[n0 + tid];
    }
    for (int i = tid; i < 512; i += 256) {
        int q = i >> 6, j = i & 63;
        sp[256 + i] = W3[q * HIDSZ + n0 + j];
    }
    if (tid < 128)
        ((float4*)(sp + 768))[tid] = ((const float4*)(g_z2 + (size_t)m0 * 8))[tid];
    __syncthreads();

    const int lr = (lane >> 2);           // 0..7
    const int lc = (lane & 3) * 2;        // 0,2,4,6
#pragma unroll
    for (int mt = 0; mt < 2; mt++)
#pragma unroll
        for (int rr = 0; rr < 2; rr++) {
            const int lrow = wm * 32 + mt * 16 + rr * 8 + lr;     // 0..63
            const int grow = m0 + lrow;
            const float* z2p = sp + 768 + lrow * 8;
#pragma unroll
            for (int nt = 0; nt < 2; nt++) {
                const int lcol = wn * 16 + nt * 8 + lc;           // 0..63
                const size_t o = (size_t)grow * HIDSZ + n0 + lcol;
                float2 cv = *(const float2*)&c[o];
                float hn[2], cn[2], fv[2];
#pragma unroll
                for (int j = 0; j < 2; j++) {
                    const int col = lcol + j;
                    float ii = sigm(acc[0][mt][nt][rr * 2 + j] + sp[col]);
                    float gg = tanh_(acc[1][mt][nt][rr * 2 + j] + sp[64 + col]);
                    float oo = sigm(acc[2][mt][nt][rr * 2 + j] + sp[128 + col]);
                    float sf = sp[192 + col];
#pragma unroll
                    for (int q = 0; q < 8; q++)
                        sf = fmaf(z2p[q], sp[256 + q * 64 + col], sf);
                    float ff = sigm(sf);
                    float cN = fmaf(ff, (j ? cv.y : cv.x), ii * gg);
                    hn[j] = oo * tanh_(cN);
                    cn[j] = cN;
                    fv[j] = ff;
                }
                *(float2*)&out[o]          = make_float2(hn[0], hn[1]);
                *(float2*)&out[BH + o]     = make_float2(cn[0], cn[1]);
                *(float2*)&out[2 * (size_t)BH + o] = make_float2(fv[0], fv[1]);
            }
        }
}

// ---------------------------------------------------------------------------
extern "C" void kernel_launch(void* const* d_in, const int* in_sizes, int n_in,
                              void* d_out, int out_size)
{
    const float* x    = (const float*)d_in[0];
    const float* h    = (const float*)d_in[1];
    const float* c    = (const float*)d_in[2];
    const float* W_hi = (const float*)d_in[3];
    const float* W_xi = (const float*)d_in[4];
    const float* b_i  = (const float*)d_in[5];
    const float* W_hc = (const float*)d_in[6];
    const float* W_xc = (const float*)d_in[7];
    const float* b_c  = (const float*)d_in[8];
    const float* W_ho = (const float*)d_in[9];
    const float* W_xo = (const float*)d_in[10];
    const float* b_o  = (const float*)d_in[11];
    const float* W1   = (const float*)d_in[12];
    const float* b1   = (const float*)d_in[13];
    const float* W2   = (const float*)d_in[14];
    const float* b2   = (const float*)d_in[15];
    const float* W3   = (const float*)d_in[16];
    const float* b3   = (const float*)d_in[17];
    float* out = (float*)d_out;

    cudaFuncSetAttribute(mlp_kernel, cudaFuncAttributeMaxDynamicSharedMemorySize,
                         16 * KTOT * (int)sizeof(float));
    cudaFuncSetAttribute(gemm_fused, cudaFuncAttributeMaxDynamicSharedMemorySize,
                         SMEM_TOTAL);

    // fork: convA on main stream; convW and mlp on side streams
    cudaEventRecord(g_gs.evRoot, 0);
    cudaStreamWaitEvent(g_gs.sW, g_gs.evRoot, 0);
    cudaStreamWaitEvent(g_gs.sM, g_gs.evRoot, 0);

    convA<<<(BATCH * KTOT / 4) / 256, 256>>>(x, h);
    convW<<<dim3(32, 32, 6), dim3(32, 8), 0, g_gs.sW>>>(W_xi, W_hi, W_xc, W_hc, W_xo, W_ho);
    mlp_kernel<<<256, 256, 16 * KTOT * sizeof(float), g_gs.sM>>>(x, h, W1, b1, W2, b2);

    // fused gemm needs convA (same stream) + convW + mlp (joins)
    cudaEventRecord(g_gs.evW, g_gs.sW);
    cudaEventRecord(g_gs.evM, g_gs.sM);
    cudaStreamWaitEvent(0, g_gs.evW, 0);
    cudaStreamWaitEvent(0, g_gs.evM, 0);

    dim3 grid(HIDSZ / BN, BATCH / BM);   // (16, 128)
    gemm_fused<<<grid, 256, SMEM_TOTAL>>>(c, b_i, b_c, b_o, W3, b3, out);
}

// round 16
// speedup vs baseline: 1.2664x; 1.2047x over previous
#include <cuda_runtime.h>
#include <cuda_fp16.h>
#include <cstdint>
#include <math.h>

// -------------------- problem constants --------------------
#define BATCH   8192
#define INSZ    1024
#define HIDSZ   1024
#define KTOT    2048
#define BH      (BATCH * HIDSZ)

// -------------------- GEMM tiling --------------------
#define BM 64
#define BN 64
#define BK 64
#define KITERS (KTOT / BK)          // 32
#define RS 144                      // smem row stride bytes (128B data + 16B pad)
#define TILEA (64 * RS)             // 9216 (A, BM rows)
#define TILEB (64 * RS)             // 9216 (one gate's B, BN rows)
#define STAGE_BYTES (TILEA + 3 * TILEB)   // 36864
#define SMEM_TOTAL (2 * STAGE_BYTES)      // 73728 (3 CTAs/SM: 216KB)

// -------------------- device scratch --------------------
__device__ __align__(16) __half gAh[(size_t)BATCH * KTOT];       // A (fp16)
__device__ __align__(16) __half gW [(size_t)3 * HIDSZ * KTOT];   // W^T: [g][n][k]
__device__ __align__(16) float  g_z2[BATCH * 8];

// -------------------- streams/events for graph fork-join --------------------
namespace {
struct GraphStreams {
    cudaStream_t sW = nullptr, sM = nullptr;
    cudaEvent_t evRoot = nullptr, evW = nullptr, evM = nullptr;
    GraphStreams() {
        cudaStreamCreateWithFlags(&sW, cudaStreamNonBlocking);
        cudaStreamCreateWithFlags(&sM, cudaStreamNonBlocking);
        cudaEventCreateWithFlags(&evRoot, cudaEventDisableTiming);
        cudaEventCreateWithFlags(&evW, cudaEventDisableTiming);
        cudaEventCreateWithFlags(&evM, cudaEventDisableTiming);
    }
};
GraphStreams g_gs;
}

// -------------------- helpers --------------------
__device__ __forceinline__ uint32_t smem_u32(const void* p) {
    uint32_t a;
    asm("{ .reg .u64 t; cvta.to.shared.u64 t, %1; cvt.u32.u64 %0, t; }" : "=r"(a) : "l"(p));
    return a;
}
#define CPASYNC16(dst, src) \
    asm volatile("cp.async.cg.shared.global [%0], [%1], 16;" :: "r"(dst), "l"(src))
#define CP_COMMIT() asm volatile("cp.async.commit_group;")
#define CP_WAIT0()  asm volatile("cp.async.wait_group 0;")

__device__ __forceinline__ void ldmx4(uint32_t addr, uint32_t& r0, uint32_t& r1,
                                      uint32_t& r2, uint32_t& r3) {
    asm volatile("ldmatrix.sync.aligned.m8n8.x4.shared.b16 {%0,%1,%2,%3}, [%4];"
                 : "=r"(r0), "=r"(r1), "=r"(r2), "=r"(r3) : "r"(addr));
}
__device__ __forceinline__ void mma16816(float* d, const uint32_t* a, const uint32_t* b) {
    asm volatile(
        "mma.sync.aligned.m16n8k16.row.col.f32.f16.f16.f32 "
        "{%0,%1,%2,%3}, {%4,%5,%6,%7}, {%8,%9}, {%0,%1,%2,%3};"
        : "+f"(d[0]), "+f"(d[1]), "+f"(d[2]), "+f"(d[3])
        : "r"(a[0]), "r"(a[1]), "r"(a[2]), "r"(a[3]), "r"(b[0]), "r"(b[1]));
}

__device__ __forceinline__ float sigm(float x) { return 1.0f / (1.0f + __expf(-x)); }
__device__ __forceinline__ float tanh_(float x) {
    float t = __expf(2.0f * x);
    return 1.0f - 2.0f / (t + 1.0f);
}

// ---------------------------------------------------------------------------
// convert A = concat(x, h) -> fp16
// ---------------------------------------------------------------------------
__global__ void convA(const float* __restrict__ x, const float* __restrict__ h) {
    int idx = blockIdx.x * blockDim.x + threadIdx.x;   // float4 index
    int row = idx >> 9;                                 // KTOT/4 = 512
    int k   = (idx & 511) * 4;
    float4 v = (k < INSZ)
        ? *(const float4*)(x + (size_t)row * INSZ + k)
        : *(const float4*)(h + (size_t)row * HIDSZ + (k - INSZ));
    size_t o = (size_t)row * KTOT + k;
    __half2* dh = (__half2*)(gAh + o);
    dh[0] = __halves2half2(__float2half_rn(v.x), __float2half_rn(v.y));
    dh[1] = __halves2half2(__float2half_rn(v.z), __float2half_rn(v.w));
}

// ---------------------------------------------------------------------------
// transpose weights: gW[g][n][k] = W[k][n]   (mat = g*2 + half, half0=Wx,1=Wh)
// ---------------------------------------------------------------------------
__global__ void convW(const float* __restrict__ Wxi, const float* __restrict__ Whi,
                      const float* __restrict__ Wxc, const float* __restrict__ Whc,
                      const float* __restrict__ Wxo, const float* __restrict__ Who) {
    __shared__ float t[32][33];
    int mat = blockIdx.z;
    const float* src;
    switch (mat) {
        case 0: src = Wxi; break; case 1: src = Whi; break;
        case 2: src = Wxc; break; case 3: src = Whc; break;
        case 4: src = Wxo; break; default: src = Who; break;
    }
    int n0 = blockIdx.x * 32, k0 = blockIdx.y * 32;
    int tx = threadIdx.x, ty = threadIdx.y;   // 32 x 8
#pragma unroll
    for (int j = 0; j < 4; j++)
        t[ty + j * 8][tx] = src[(size_t)(k0 + ty + j * 8) * HIDSZ + n0 + tx];
    __syncthreads();
    int g = mat >> 1, half = mat & 1;
#pragma unroll
    for (int j = 0; j < 4; j++) {
        int n = n0 + ty + j * 8, k = k0 + tx;
        size_t o = ((size_t)(g * HIDSZ + n)) * KTOT + half * INSZ + k;
        gW[o] = __float2half_rn(t[tx][ty + j * 8]);
    }
}

// ---------------------------------------------------------------------------
// forget-gate MLP front half: z2 = relu(relu(xh@W1+b1)@W2+b2)
// No smem: W1 read from global (L2-resident), each warp handles 4 rows so
// every W1 fetch is reused 4x.  High occupancy, FMA/L2-bound.
// grid 256 x 256: warp w handles rows [4w, 4w+4)
// ---------------------------------------------------------------------------
__global__ void mlp_kernel(const float* __restrict__ x, const float* __restrict__ h,
                           const float* __restrict__ W1, const float* __restrict__ b1,
                           const float* __restrict__ W2, const float* __restrict__ b2)
{
    const int warp = (blockIdx.x * blockDim.x + threadIdx.x) >> 5;
    const int lane = threadIdx.x & 31;
    const int row0 = warp * 4;
    if (row0 >= BATCH) return;

    float b1r[16];
#pragma unroll
    for (int j = 0; j < 16; j++) b1r[j] = b1[j];
    float w2r[16];
    float b2r = 0.0f;
    if (lane < 8) {
        b2r = b2[lane];
#pragma unroll
        for (int j = 0; j < 16; j++) w2r[j] = W2[j * 8 + lane];
    }

    float acc[4][16];
#pragma unroll
    for (int r = 0; r < 4; r++)
#pragma unroll
        for (int j = 0; j < 16; j++) acc[r][j] = 0.0f;

#pragma unroll 1
    for (int i = 0; i < KTOT / 32; i++) {
        const int k = i * 32 + lane;
        // W1 row k: 16 consecutive floats (coalesced float4 x4; L2-hot)
        float4 w0 = *(const float4*)&W1[k * 16];
        float4 w1 = *(const float4*)&W1[k * 16 + 4];
        float4 w2v = *(const float4*)&W1[k * 16 + 8];
        float4 w3v = *(const float4*)&W1[k * 16 + 12];
        float wv[16] = {w0.x, w0.y, w0.z, w0.w, w1.x, w1.y, w1.z, w1.w,
                        w2v.x, w2v.y, w2v.z, w2v.w, w3v.x, w3v.y, w3v.z, w3v.w};
        float v[4];
#pragma unroll
        for (int r = 0; r < 4; r++)
            v[r] = (k < INSZ) ? x[(size_t)(row0 + r) * INSZ + k]
                              : h[(size_t)(row0 + r) * HIDSZ + (k - INSZ)];
#pragma unroll
        for (int r = 0; r < 4; r++)
#pragma unroll
            for (int j = 0; j < 16; j++)
                acc[r][j] = fmaf(v[r], wv[j], acc[r][j]);
    }

    // butterfly reduce across lanes: every lane ends with full sums
#pragma unroll
    for (int off = 16; off; off >>= 1)
#pragma unroll
        for (int r = 0; r < 4; r++)
#pragma unroll
            for (int j = 0; j < 16; j++)
                acc[r][j] += __shfl_xor_sync(0xffffffffu, acc[r][j], off);

    if (lane < 8) {
#pragma unroll
        for (int r = 0; r < 4; r++) {
            float s = b2r;
#pragma unroll
            for (int j = 0; j < 16; j++)
                s = fmaf(fmaxf(acc[r][j] + b1r[j], 0.0f), w2r[j], s);
            g_z2[(size_t)(row0 + r) * 8 + lane] = fmaxf(s, 0.0f);
        }
    }
}

// ---------------------------------------------------------------------------
// Fused HMMA GEMM + LSTM epilogue, 2-stage pipeline, 3 CTAs/SM.
// Each CTA: 64x64 tile, ALL 3 gates, epilogue in-register, writes out.
// grid (n 16, m 128), 256 threads, warp grid 2(m) x 4(n)
// ---------------------------------------------------------------------------
__global__ __launch_bounds__(256, 3)
void gemm_fused(const float* __restrict__ c,
                const float* __restrict__ b_i, const float* __restrict__ b_c,
                const float* __restrict__ b_o,
                const float* __restrict__ W3, const float* __restrict__ b3,
                float* __restrict__ out)
{
    extern __shared__ char smem[];
    const uint32_t sbase = smem_u32(smem);

    const int tid = threadIdx.x;
    const int wid = tid >> 5, lane = tid & 31;
    const int wm = wid & 1, wn = wid >> 1;          // warp coords: 2(m) x 4(n)
    const int m0 = blockIdx.y * BM;
    const int n0 = blockIdx.x * BN;

    const __half* Ah = gAh + (size_t)m0 * KTOT;
    const __half* Bp = gW + (size_t)n0 * KTOT;       // gate g at + g*HIDSZ*KTOT

    auto copy_stage = [&](int kt, int s) {
        const uint32_t base = sbase + s * STAGE_BYTES;
        const int koff = kt * BK;
#pragma unroll
        for (int i = tid; i < 512; i += 256) {
            int row = i >> 3, ch = i & 7;
            uint32_t d = base + row * RS + ch * 16;
            const size_t go = (size_t)row * KTOT + koff + ch * 8;
            CPASYNC16(d, Ah + go);
#pragma unroll
            for (int g = 0; g < 3; g++)
                CPASYNC16(d + TILEA + g * TILEB, Bp + (size_t)g * HIDSZ * KTOT + go);
        }
    };

    float acc[3][2][2][4];
#pragma unroll
    for (int g = 0; g < 3; g++)
#pragma unroll
        for (int mt = 0; mt < 2; mt++)
#pragma unroll
            for (int nt = 0; nt < 2; nt++)
#pragma unroll
                for (int r = 0; r < 4; r++) acc[g][mt][nt][r] = 0.0f;

    // ldmatrix address components
    const uint32_t aRowOff = (uint32_t)((wm * 32 + (lane & 15)) * RS + ((lane >> 4) & 1) * 16);
    const uint32_t bRowOff = (uint32_t)((wn * 16 + (lane & 7) + ((lane >> 4) & 1) * 8) * RS
                                        + ((lane >> 3) & 1) * 16);

    copy_stage(0, 0);
    CP_COMMIT();

    for (int kt = 0; kt < KITERS; kt++) {
        const int s = kt & 1;
        CP_WAIT0();
        __syncthreads();
        if (kt + 1 < KITERS) { copy_stage(kt + 1, s ^ 1); CP_COMMIT(); }

        const uint32_t base = sbase + s * STAGE_BYTES;
        const uint32_t aB = base + aRowOff;
        const uint32_t bB = base + TILEA + bRowOff;

#pragma unroll
        for (int ks = 0; ks < 4; ks++) {
            const uint32_t kb = (uint32_t)(ks * 32);
            uint32_t a[2][4];
#pragma unroll
            for (int mt = 0; mt < 2; mt++)
                ldmx4(aB + mt * 16 * RS + kb, a[mt][0], a[mt][1], a[mt][2], a[mt][3]);
#pragma unroll
            for (int g = 0; g < 3; g++) {
                uint32_t b[4];
                ldmx4(bB + g * TILEB + kb, b[0], b[1], b[2], b[3]);   // nt 0,1
#pragma unroll
                for (int mt = 0; mt < 2; mt++)
#pragma unroll
                    for (int nt = 0; nt < 2; nt++)
                        mma16816(acc[g][mt][nt], a[mt], &b[nt * 2]);
            }
        }
        __syncthreads();
    }

    // -------------------- fused epilogue --------------------
    float* sp = (float*)smem;  // bi[64] bc[64] bo[64] b3[64] W3[8][64] z2[64][8]
    if (tid < 64) {
        sp[tid]       = b_i[n0 + tid];
        sp[64 + tid]  = b_c[n0 + tid];
        sp[128 + tid] = b_o[n0 + tid];
        sp[192 + tid] = b3[n0 + tid];
    }
    for (int i = tid; i < 512; i += 256) {
        int q = i >> 6, j = i & 63;
        sp[256 + i] = W3[q * HIDSZ + n0 + j];
    }
    if (tid < 128)
        ((float4*)(sp + 768))[tid] = ((const float4*)(g_z2 + (size_t)m0 * 8))[tid];
    __syncthreads();

    const int lr = (lane >> 2);           // 0..7
    const int lc = (lane & 3) * 2;        // 0,2,4,6
#pragma unroll
    for (int mt = 0; mt < 2; mt++)
#pragma unroll
        for (int rr = 0; rr < 2; rr++) {
            const int lrow = wm * 32 + mt * 16 + rr * 8 + lr;     // 0..63
            const int grow = m0 + lrow;
            const float* z2p = sp + 768 + lrow * 8;
#pragma unroll
            for (int nt = 0; nt < 2; nt++) {
                const int lcol = wn * 16 + nt * 8 + lc;           // 0..63
                const size_t o = (size_t)grow * HIDSZ + n0 + lcol;
                float2 cv = *(const float2*)&c[o];
                float hn[2], cn[2], fv[2];
#pragma unroll
                for (int j = 0; j < 2; j++) {
                    const int col = lcol + j;
                    float ii = sigm(acc[0][mt][nt][rr * 2 + j] + sp[col]);
                    float gg = tanh_(acc[1][mt][nt][rr * 2 + j] + sp[64 + col]);
                    float oo = sigm(acc[2][mt][nt][rr * 2 + j] + sp[128 + col]);
                    float sf = sp[192 + col];
#pragma unroll
                    for (int q = 0; q < 8; q++)
                        sf = fmaf(z2p[q], sp[256 + q * 64 + col], sf);
                    float ff = sigm(sf);
                    float cN = fmaf(ff, (j ? cv.y : cv.x), ii * gg);
                    hn[j] = oo * tanh_(cN);
                    cn[j] = cN;
                    fv[j] = ff;
                }
                *(float2*)&out[o]          = make_float2(hn[0], hn[1]);
                *(float2*)&out[BH + o]     = make_float2(cn[0], cn[1]);
                *(float2*)&out[2 * (size_t)BH + o] = make_float2(fv[0], fv[1]);
            }
        }
}

// ---------------------------------------------------------------------------
extern "C" void kernel_launch(void* const* d_in, const int* in_sizes, int n_in,
                              void* d_out, int out_size)
{
    const float* x    = (const float*)d_in[0];
    const float* h    = (const float*)d_in[1];
    const float* c    = (const float*)d_in[2];
    const float* W_hi = (const float*)d_in[3];
    const float* W_xi = (const float*)d_in[4];
    const float* b_i  = (const float*)d_in[5];
    const float* W_hc = (const float*)d_in[6];
    const float* W_xc = (const float*)d_in[7];
    const float* b_c  = (const float*)d_in[8];
    const float* W_ho = (const float*)d_in[9];
    const float* W_xo = (const float*)d_in[10];
    const float* b_o  = (const float*)d_in[11];
    const float* W1   = (const float*)d_in[12];
    const float* b1   = (const float*)d_in[13];
    const float* W2   = (const float*)d_in[14];
    const float* b2   = (const float*)d_in[15];
    const float* W3   = (const float*)d_in[16];
    const float* b3   = (const float*)d_in[17];
    float* out = (float*)d_out;

    cudaFuncSetAttribute(gemm_fused, cudaFuncAttributeMaxDynamicSharedMemorySize,
                         SMEM_TOTAL);

    // fork: convA on main stream; convW and mlp on side streams
    cudaEventRecord(g_gs.evRoot, 0);
    cudaStreamWaitEvent(g_gs.sW, g_gs.evRoot, 0);
    cudaStreamWaitEvent(g_gs.sM, g_gs.evRoot, 0);

    convA<<<(BATCH * KTOT / 4) / 256, 256>>>(x, h);
    convW<<<dim3(32, 32, 6), dim3(32, 8), 0, g_gs.sW>>>(W_xi, W_hi, W_xc, W_hc, W_xo, W_ho);
    mlp_kernel<<<BATCH / 32, 256, 0, g_gs.sM>>>(x, h, W1, b1, W2, b2);   // 256 blocks

    // fused gemm needs convA (same stream) + convW + mlp (joins)
    cudaEventRecord(g_gs.evW, g_gs.sW);
    cudaEventRecord(g_gs.evM, g_gs.sM);
    cudaStreamWaitEvent(0, g_gs.evW, 0);
    cudaStreamWaitEvent(0, g_gs.evM, 0);

    dim3 grid(HIDSZ / BN, BATCH / BM);   // (16, 128)
    gemm_fused<<<grid, 256, SMEM_TOTAL>>>(c, b_i, b_c, b_o, W3, b3, out);
}

// round 17
// speedup vs baseline: 1.2686x; 1.0017x over previous
#include <cuda_runtime.h>
#include <cuda_fp16.h>
#include <cstdint>
#include <math.h>

// -------------------- problem constants --------------------
#define BATCH   8192
#define INSZ    1024
#define HIDSZ   1024
#define KTOT    2048
#define BH      (BATCH * HIDSZ)

// -------------------- GEMM tiling --------------------
#define BM 64
#define BN 64
#define BK 64
#define KITERS (KTOT / BK)          // 32
#define RS 144                      // smem row stride bytes (128B data + 16B pad)
#define TILEA (64 * RS)             // 9216 (A, BM rows)
#define TILEB (64 * RS)             // 9216 (one gate's B, BN rows)
#define STAGE_BYTES (TILEA + 3 * TILEB)   // 36864
#define SMEM_TOTAL (2 * STAGE_BYTES)      // 73728 (3 CTAs/SM: 216KB)

// -------------------- device scratch --------------------
__device__ __align__(16) __half gAh[(size_t)BATCH * KTOT];       // A (fp16)
__device__ __align__(16) __half gW [(size_t)3 * HIDSZ * KTOT];   // W^T: [g][n][k]
__device__ __align__(16) float  g_z2[BATCH * 8];

// -------------------- streams/events for graph fork-join --------------------
namespace {
struct GraphStreams {
    cudaStream_t sW = nullptr, sM = nullptr;
    cudaEvent_t evRoot = nullptr, evW = nullptr, evM = nullptr;
    GraphStreams() {
        cudaStreamCreateWithFlags(&sW, cudaStreamNonBlocking);
        cudaStreamCreateWithFlags(&sM, cudaStreamNonBlocking);
        cudaEventCreateWithFlags(&evRoot, cudaEventDisableTiming);
        cudaEventCreateWithFlags(&evW, cudaEventDisableTiming);
        cudaEventCreateWithFlags(&evM, cudaEventDisableTiming);
    }
};
GraphStreams g_gs;
}

// -------------------- helpers --------------------
__device__ __forceinline__ uint32_t smem_u32(const void* p) {
    uint32_t a;
    asm("{ .reg .u64 t; cvta.to.shared.u64 t, %1; cvt.u32.u64 %0, t; }" : "=r"(a) : "l"(p));
    return a;
}
#define CPASYNC16(dst, src) \
    asm volatile("cp.async.cg.shared.global [%0], [%1], 16;" :: "r"(dst), "l"(src))
#define CP_COMMIT() asm volatile("cp.async.commit_group;")
#define CP_WAIT0()  asm volatile("cp.async.wait_group 0;")

__device__ __forceinline__ void ldmx4(uint32_t addr, uint32_t& r0, uint32_t& r1,
                                      uint32_t& r2, uint32_t& r3) {
    asm volatile("ldmatrix.sync.aligned.m8n8.x4.shared.b16 {%0,%1,%2,%3}, [%4];"
                 : "=r"(r0), "=r"(r1), "=r"(r2), "=r"(r3) : "r"(addr));
}
__device__ __forceinline__ void mma16816(float* d, const uint32_t* a, const uint32_t* b) {
    asm volatile(
        "mma.sync.aligned.m16n8k16.row.col.f32.f16.f16.f32 "
        "{%0,%1,%2,%3}, {%4,%5,%6,%7}, {%8,%9}, {%0,%1,%2,%3};"
        : "+f"(d[0]), "+f"(d[1]), "+f"(d[2]), "+f"(d[3])
        : "r"(a[0]), "r"(a[1]), "r"(a[2]), "r"(a[3]), "r"(b[0]), "r"(b[1]));
}

__device__ __forceinline__ float sigm(float x) { return 1.0f / (1.0f + __expf(-x)); }
__device__ __forceinline__ float tanh_(float x) {
    float t = __expf(2.0f * x);
    return 1.0f - 2.0f / (t + 1.0f);
}

// ---------------------------------------------------------------------------
// transpose weights: gW[g][n][k] = W[k][n]   (mat = g*2 + half, half0=Wx,1=Wh)
// ---------------------------------------------------------------------------
__global__ void convW(const float* __restrict__ Wxi, const float* __restrict__ Whi,
                      const float* __restrict__ Wxc, const float* __restrict__ Whc,
                      const float* __restrict__ Wxo, const float* __restrict__ Who) {
    __shared__ float t[32][33];
    int mat = blockIdx.z;
    const float* src;
    switch (mat) {
        case 0: src = Wxi; break; case 1: src = Whi; break;
        case 2: src = Wxc; break; case 3: src = Whc; break;
        case 4: src = Wxo; break; default: src = Who; break;
    }
    int n0 = blockIdx.x * 32, k0 = blockIdx.y * 32;
    int tx = threadIdx.x, ty = threadIdx.y;   // 32 x 8
#pragma unroll
    for (int j = 0; j < 4; j++)
        t[ty + j * 8][tx] = src[(size_t)(k0 + ty + j * 8) * HIDSZ + n0 + tx];
    __syncthreads();
    int g = mat >> 1, half = mat & 1;
#pragma unroll
    for (int j = 0; j < 4; j++) {
        int n = n0 + ty + j * 8, k = k0 + tx;
        size_t o = ((size_t)(g * HIDSZ + n)) * KTOT + half * INSZ + k;
        gW[o] = __float2half_rn(t[tx][ty + j * 8]);
    }
}

// ---------------------------------------------------------------------------
// Fused: forget-MLP front half AND A -> fp16 conversion (one pass over x,h).
// No smem; W1 from global (L2-hot), each warp handles 4 rows (4x W1 reuse).
// grid 256 x 256: warp w handles rows [4w, 4w+4)
// ---------------------------------------------------------------------------
__global__ void mlp_kernel(const float* __restrict__ x, const float* __restrict__ h,
                           const float* __restrict__ W1, const float* __restrict__ b1,
                           const float* __restrict__ W2, const float* __restrict__ b2)
{
    const int warp = (blockIdx.x * blockDim.x + threadIdx.x) >> 5;
    const int lane = threadIdx.x & 31;
    const int row0 = warp * 4;
    if (row0 >= BATCH) return;

    float b1r[16];
#pragma unroll
    for (int j = 0; j < 16; j++) b1r[j] = b1[j];
    float w2r[16];
    float b2r = 0.0f;
    if (lane < 8) {
        b2r = b2[lane];
#pragma unroll
        for (int j = 0; j < 16; j++) w2r[j] = W2[j * 8 + lane];
    }

    float acc[4][16];
#pragma unroll
    for (int r = 0; r < 4; r++)
#pragma unroll
        for (int j = 0; j < 16; j++) acc[r][j] = 0.0f;

#pragma unroll 1
    for (int i = 0; i < KTOT / 32; i++) {
        const int k = i * 32 + lane;
        float4 w0 = *(const float4*)&W1[k * 16];
        float4 w1 = *(const float4*)&W1[k * 16 + 4];
        float4 w2v = *(const float4*)&W1[k * 16 + 8];
        float4 w3v = *(const float4*)&W1[k * 16 + 12];
        float wv[16] = {w0.x, w0.y, w0.z, w0.w, w1.x, w1.y, w1.z, w1.w,
                        w2v.x, w2v.y, w2v.z, w2v.w, w3v.x, w3v.y, w3v.z, w3v.w};
        float v[4];
#pragma unroll
        for (int r = 0; r < 4; r++) {
            v[r] = (k < INSZ) ? x[(size_t)(row0 + r) * INSZ + k]
                              : h[(size_t)(row0 + r) * HIDSZ + (k - INSZ)];
            gAh[(size_t)(row0 + r) * KTOT + k] = __float2half_rn(v[r]);  // fused conv
        }
#pragma unroll
        for (int r = 0; r < 4; r++)
#pragma unroll
            for (int j = 0; j < 16; j++)
                acc[r][j] = fmaf(v[r], wv[j], acc[r][j]);
    }

#pragma unroll
    for (int off = 16; off; off >>= 1)
#pragma unroll
        for (int r = 0; r < 4; r++)
#pragma unroll
            for (int j = 0; j < 16; j++)
                acc[r][j] += __shfl_xor_sync(0xffffffffu, acc[r][j], off);

    if (lane < 8) {
#pragma unroll
        for (int r = 0; r < 4; r++) {
            float s = b2r;
#pragma unroll
            for (int j = 0; j < 16; j++)
                s = fmaf(fmaxf(acc[r][j] + b1r[j], 0.0f), w2r[j], s);
            g_z2[(size_t)(row0 + r) * 8 + lane] = fmaxf(s, 0.0f);
        }
    }
}

// ---------------------------------------------------------------------------
// Fused HMMA GEMM + LSTM epilogue, 2-stage pipeline, 3 CTAs/SM.
// Single barrier per k-iter (end-of-loop barrier proven redundant).
// grid (n 16, m 128), 256 threads, warp grid 2(m) x 4(n)
// ---------------------------------------------------------------------------
__global__ __launch_bounds__(256, 3)
void gemm_fused(const float* __restrict__ c,
                const float* __restrict__ b_i, const float* __restrict__ b_c,
                const float* __restrict__ b_o,
                const float* __restrict__ W3, const float* __restrict__ b3,
                float* __restrict__ out)
{
    extern __shared__ char smem[];
    const uint32_t sbase = smem_u32(smem);

    const int tid = threadIdx.x;
    const int wid = tid >> 5, lane = tid & 31;
    const int wm = wid & 1, wn = wid >> 1;          // warp coords: 2(m) x 4(n)
    const int m0 = blockIdx.y * BM;
    const int n0 = blockIdx.x * BN;

    const __half* Ah = gAh + (size_t)m0 * KTOT;
    const __half* Bp = gW + (size_t)n0 * KTOT;       // gate g at + g*HIDSZ*KTOT

    auto copy_stage = [&](int kt, int s) {
        const uint32_t base = sbase + s * STAGE_BYTES;
        const int koff = kt * BK;
#pragma unroll
        for (int i = tid; i < 512; i += 256) {
            int row = i >> 3, ch = i & 7;
            uint32_t d = base + row * RS + ch * 16;
            const size_t go = (size_t)row * KTOT + koff + ch * 8;
            CPASYNC16(d, Ah + go);
#pragma unroll
            for (int g = 0; g < 3; g++)
                CPASYNC16(d + TILEA + g * TILEB, Bp + (size_t)g * HIDSZ * KTOT + go);
        }
    };

    float acc[3][2][2][4];
#pragma unroll
    for (int g = 0; g < 3; g++)
#pragma unroll
        for (int mt = 0; mt < 2; mt++)
#pragma unroll
            for (int nt = 0; nt < 2; nt++)
#pragma unroll
                for (int r = 0; r < 4; r++) acc[g][mt][nt][r] = 0.0f;

    // ldmatrix address components
    const uint32_t aRowOff = (uint32_t)((wm * 32 + (lane & 15)) * RS + ((lane >> 4) & 1) * 16);
    const uint32_t bRowOff = (uint32_t)((wn * 16 + (lane & 7) + ((lane >> 4) & 1) * 8) * RS
                                        + ((lane >> 3) & 1) * 16);

    copy_stage(0, 0);
    CP_COMMIT();

    for (int kt = 0; kt < KITERS; kt++) {
        const int s = kt & 1;
        CP_WAIT0();
        __syncthreads();   // single barrier: data visibility + overwrite guard
        if (kt + 1 < KITERS) { copy_stage(kt + 1, s ^ 1); CP_COMMIT(); }

        const uint32_t base = sbase + s * STAGE_BYTES;
        const uint32_t aB = base + aRowOff;
        const uint32_t bB = base + TILEA + bRowOff;

#pragma unroll
        for (int ks = 0; ks < 4; ks++) {
            const uint32_t kb = (uint32_t)(ks * 32);
            uint32_t a[2][4];
#pragma unroll
            for (int mt = 0; mt < 2; mt++)
                ldmx4(aB + mt * 16 * RS + kb, a[mt][0], a[mt][1], a[mt][2], a[mt][3]);
#pragma unroll
            for (int g = 0; g < 3; g++) {
                uint32_t b[4];
                ldmx4(bB + g * TILEB + kb, b[0], b[1], b[2], b[3]);   // nt 0,1
#pragma unroll
                for (int mt = 0; mt < 2; mt++)
#pragma unroll
                    for (int nt = 0; nt < 2; nt++)
                        mma16816(acc[g][mt][nt], a[mt], &b[nt * 2]);
            }
        }
        // no trailing barrier: next iter's top barrier orders reads vs overwrite
    }

    // -------------------- fused epilogue --------------------
    // sp occupies the first 5.1KB of stage 0; last mainloop iter reads stage 1,
    // and all warps passed the top barrier of the final iter -> no conflict.
    float* sp = (float*)smem;  // bi[64] bc[64] bo[64] b3[64] W3[8][64] z2[64][8]
    if (tid < 64) {
        sp[tid]       = b_i[n0 + tid];
        sp[64 + tid]  = b_c[n0 + tid];
        sp[128 + tid] = b_o[n0 + tid];
        sp[192 + tid] = b3[n0 + tid];
    }
    for (int i = tid; i < 512; i += 256) {
        int q = i >> 6, j = i & 63;
        sp[256 + i] = W3[q * HIDSZ + n0 + j];
    }
    if (tid < 128)
        ((float4*)(sp + 768))[tid] = ((const float4*)(g_z2 + (size_t)m0 * 8))[tid];
    __syncthreads();

    const int lr = (lane >> 2);           // 0..7
    const int lc = (lane & 3) * 2;        // 0,2,4,6
#pragma unroll
    for (int mt = 0; mt < 2; mt++)
#pragma unroll
        for (int rr = 0; rr < 2; rr++) {
            const int lrow = wm * 32 + mt * 16 + rr * 8 + lr;     // 0..63
            const int grow = m0 + lrow;
            const float* z2p = sp + 768 + lrow * 8;
#pragma unroll
            for (int nt = 0; nt < 2; nt++) {
                const int lcol = wn * 16 + nt * 8 + lc;           // 0..63
                const size_t o = (size_t)grow * HIDSZ + n0 + lcol;
                float2 cv = *(const float2*)&c[o];
                float hn[2], cn[2], fv[2];
#pragma unroll
                for (int j = 0; j < 2; j++) {
                    const int col = lcol + j;
                    float ii = sigm(acc[0][mt][nt][rr * 2 + j] + sp[col]);
                    float gg = tanh_(acc[1][mt][nt][rr * 2 + j] + sp[64 + col]);
                    float oo = sigm(acc[2][mt][nt][rr * 2 + j] + sp[128 + col]);
                    float sf = sp[192 + col];
#pragma unroll
                    for (int q = 0; q < 8; q++)
                        sf = fmaf(z2p[q], sp[256 + q * 64 + col], sf);
                    float ff = sigm(sf);
                    float cN = fmaf(ff, (j ? cv.y : cv.x), ii * gg);
                    hn[j] = oo * tanh_(cN);
                    cn[j] = cN;
                    fv[j] = ff;
                }
                *(float2*)&out[o]          = make_float2(hn[0], hn[1]);
                *(float2*)&out[BH + o]     = make_float2(cn[0], cn[1]);
                *(float2*)&out[2 * (size_t)BH + o] = make_float2(fv[0], fv[1]);
            }
        }
}

// ---------------------------------------------------------------------------
extern "C" void kernel_launch(void* const* d_in, const int* in_sizes, int n_in,
                              void* d_out, int out_size)
{
    const float* x    = (const float*)d_in[0];
    const float* h    = (const float*)d_in[1];
    const float* c    = (const float*)d_in[2];
    const float* W_hi = (const float*)d_in[3];
    const float* W_xi = (const float*)d_in[4];
    const float* b_i  = (const float*)d_in[5];
    const float* W_hc = (const float*)d_in[6];
    const float* W_xc = (const float*)d_in[7];
    const float* b_c  = (const float*)d_in[8];
    const float* W_ho = (const float*)d_in[9];
    const float* W_xo = (const float*)d_in[10];
    const float* b_o  = (const float*)d_in[11];
    const float* W1   = (const float*)d_in[12];
    const float* b1   = (const float*)d_in[13];
    const float* W2   = (const float*)d_in[14];
    const float* b2   = (const float*)d_in[15];
    const float* W3   = (const float*)d_in[16];
    const float* b3   = (const float*)d_in[17];
    float* out = (float*)d_out;

    cudaFuncSetAttribute(gemm_fused, cudaFuncAttributeMaxDynamicSharedMemorySize,
                         SMEM_TOTAL);

    // fork: mlp(+convA) on main stream; convW on side stream
    cudaEventRecord(g_gs.evRoot, 0);
    cudaStreamWaitEvent(g_gs.sW, g_gs.evRoot, 0);

    mlp_kernel<<<BATCH / 32, 256>>>(x, h, W1, b1, W2, b2);   // writes gAh + g_z2
    convW<<<dim3(32, 32, 6), dim3(32, 8), 0, g_gs.sW>>>(W_xi, W_hi, W_xc, W_hc, W_xo, W_ho);

    // fused gemm needs mlp (same stream) + convW (join)
    cudaEventRecord(g_gs.evW, g_gs.sW);
    cudaStreamWaitEvent(0, g_gs.evW, 0);

    dim3 grid(HIDSZ / BN, BATCH / BM);   // (16, 128)
    gemm_fused<<<grid, 256, SMEM_TOTAL>>>(c, b_i, b_c, b_o, W3, b3, out);
}